// round 4
// baseline (speedup 1.0000x reference)
#include <cuda_runtime.h>
#include <cuda_bf16.h>

#define N_NODES 1000000
#define N_EDGES 32000000

// Scratch: per-node aggregation buffer (initialized to (1+eps)*x, then
// edge contributions are RED.ADD'ed in).
__device__ float g_agg[N_NODES];

// ---------------------------------------------------------------------------
// Kernel 1: agg[i] = (1 + eps) * x[i]   (fuses the self-term with the zeroing)
// ---------------------------------------------------------------------------
__global__ void init_agg_kernel(const float* __restrict__ x,
                                const float* __restrict__ eps) {
    const float e = 1.0f + *eps;
    int idx = (blockIdx.x * blockDim.x + threadIdx.x) * 4;
    if (idx < N_NODES) {           // N_NODES % 4 == 0, float4 always in-bounds
        float4 v = *reinterpret_cast<const float4*>(x + idx);
        float4 r;
        r.x = e * v.x; r.y = e * v.y; r.z = e * v.z; r.w = e * v.w;
        *reinterpret_cast<float4*>(g_agg + idx) = r;
    }
}

// ---------------------------------------------------------------------------
// Kernel 2: for each edge (s, d): agg[d] += x[s]
// 8 edges per thread. All index loads front-batched (4x int4, independent),
// then 8 independent gathers, then 8 REDs -> deep memory-level parallelism
// to hide the ~600-cycle DRAM index latency and keep the L1tex/LTS queues full.
// atomicAdd with discarded result -> RED.E.ADD.F32 (no return trip).
// ---------------------------------------------------------------------------
__global__ void __launch_bounds__(256)
edge_scatter_kernel(const int4* __restrict__ src4,
                    const int4* __restrict__ dst4,
                    const float* __restrict__ x) {
    int t = blockIdx.x * blockDim.x + threadIdx.x;
    int base = t * 2;   // two int4 of src + two int4 of dst = 8 edges

    // Front-batch all index loads (4 independent 16B loads)
    int4 s0 = src4[base];
    int4 s1 = src4[base + 1];
    int4 d0 = dst4[base];
    int4 d1 = dst4[base + 1];

    // 8 independent random gathers (L2-resident x)
    float v0 = __ldg(x + s0.x);
    float v1 = __ldg(x + s0.y);
    float v2 = __ldg(x + s0.z);
    float v3 = __ldg(x + s0.w);
    float v4 = __ldg(x + s1.x);
    float v5 = __ldg(x + s1.y);
    float v6 = __ldg(x + s1.z);
    float v7 = __ldg(x + s1.w);

    // 8 reductions (no return trip)
    atomicAdd(&g_agg[d0.x], v0);
    atomicAdd(&g_agg[d0.y], v1);
    atomicAdd(&g_agg[d0.z], v2);
    atomicAdd(&g_agg[d0.w], v3);
    atomicAdd(&g_agg[d1.x], v4);
    atomicAdd(&g_agg[d1.y], v5);
    atomicAdd(&g_agg[d1.z], v6);
    atomicAdd(&g_agg[d1.w], v7);
}

// ---------------------------------------------------------------------------
// Kernel 3: out[i] = MLP(agg[i])   with MLP = L(1,20)->ReLU->L(20,20)->ReLU->L(20,1)
// Weights staged to shared memory; inner 20x20 fully unrolled.
// ---------------------------------------------------------------------------
__global__ void node_mlp_kernel(const float* __restrict__ w1,
                                const float* __restrict__ b1,
                                const float* __restrict__ w2,
                                const float* __restrict__ b2,
                                const float* __restrict__ w3,
                                const float* __restrict__ b3,
                                float* __restrict__ out) {
    __shared__ float sw1[20], sb1[20], sw2[400], sb2[20], sw3[20], sb3;
    int tid = threadIdx.x;
    if (tid < 20) {
        sw1[tid] = w1[tid];
        sb1[tid] = b1[tid];
        sb2[tid] = b2[tid];
        sw3[tid] = w3[tid];
    }
    for (int i = tid; i < 400; i += blockDim.x) sw2[i] = w2[i];
    if (tid == 0) sb3 = b3[0];
    __syncthreads();

    int i = blockIdx.x * blockDim.x + tid;
    if (i < N_NODES) {
        float s = g_agg[i];

        float h1[20];
        #pragma unroll
        for (int j = 0; j < 20; j++)
            h1[j] = fmaxf(fmaf(s, sw1[j], sb1[j]), 0.0f);

        float acc_out = sb3;
        #pragma unroll
        for (int k = 0; k < 20; k++) {
            float a = sb2[k];
            #pragma unroll
            for (int j = 0; j < 20; j++)
                a = fmaf(h1[j], sw2[j * 20 + k], a);
            acc_out = fmaf(fmaxf(a, 0.0f), sw3[k], acc_out);
        }
        out[i] = acc_out;
    }
}

// ---------------------------------------------------------------------------
// Launch. Inputs (metadata order):
//   0: x          [1M]  f32
//   1: edge_index [2, 32M] int32   (src = first 32M, dst = second 32M)
//   2: eps        [1]   f32
//   3: w1 [20]  4: b1 [20]  5: w2 [400]  6: b2 [20]  7: w3 [20]  8: b3 [1]
// Output: [1M] f32
// ---------------------------------------------------------------------------
extern "C" void kernel_launch(void* const* d_in, const int* in_sizes, int n_in,
                              void* d_out, int out_size) {
    const float* x   = (const float*)d_in[0];
    const int*   ei  = (const int*)d_in[1];
    const float* eps = (const float*)d_in[2];
    const float* w1  = (const float*)d_in[3];
    const float* b1  = (const float*)d_in[4];
    const float* w2  = (const float*)d_in[5];
    const float* b2  = (const float*)d_in[6];
    const float* w3  = (const float*)d_in[7];
    const float* b3  = (const float*)d_in[8];
    float* out = (float*)d_out;

    const int4* src4 = (const int4*)ei;                 // first 32M ints
    const int4* dst4 = (const int4*)(ei + N_EDGES);     // second 32M ints

    // 1) agg = (1+eps)*x : float4 per thread
    init_agg_kernel<<<(N_NODES / 4 + 255) / 256, 256>>>(x, eps);

    // 2) edge scatter: 4M threads, 8 edges each -> exactly 32M edges
    edge_scatter_kernel<<<N_EDGES / 8 / 256, 256>>>(src4, dst4, x);

    // 3) node MLP
    node_mlp_kernel<<<(N_NODES + 255) / 256, 256>>>(w1, b1, w2, b2, w3, b3, out);
}

// round 5
// speedup vs baseline: 1.0302x; 1.0302x over previous
#include <cuda_runtime.h>
#include <cuda_bf16.h>

#define N_NODES 1000000
#define N_EDGES 32000000

// Scratch: per-node aggregation buffer (zeroed via memsetAsync, then edge
// contributions are RED.ADD'ed in; self-term handled in the MLP kernel).
__device__ float g_agg[N_NODES];

// ---------------------------------------------------------------------------
// Kernel 1: for each edge (s, d): agg[d] += x[s]
// 4 edges per thread. Index loads use __ldcs (streaming / evict-first) so the
// one-touch 256 MB index stream does not evict the hot, reused 4 MB x and
// 4 MB agg arrays from L2 — keeping the random gathers and the RED.ADD
// targets L2-resident instead of escalating to DRAM.
// atomicAdd with discarded result -> RED.E.ADD.F32 (no return trip).
// ---------------------------------------------------------------------------
__global__ void __launch_bounds__(256)
edge_scatter_kernel(const int4* __restrict__ src4,
                    const int4* __restrict__ dst4,
                    const float* __restrict__ x) {
    int t = blockIdx.x * blockDim.x + threadIdx.x;

    int4 s = __ldcs(src4 + t);   // streaming: evict-first in L2
    int4 d = __ldcs(dst4 + t);

    float v0 = __ldg(x + s.x);
    float v1 = __ldg(x + s.y);
    float v2 = __ldg(x + s.z);
    float v3 = __ldg(x + s.w);

    atomicAdd(&g_agg[d.x], v0);
    atomicAdd(&g_agg[d.y], v1);
    atomicAdd(&g_agg[d.z], v2);
    atomicAdd(&g_agg[d.w], v3);
}

// ---------------------------------------------------------------------------
// Kernel 2: out[i] = MLP((1+eps)*x[i] + agg[i])
// MLP = L(1,20)->ReLU->L(20,20)->ReLU->L(20,1), weights staged to smem,
// inner 20x20 fully unrolled (FFMA + LDS-broadcast).
// ---------------------------------------------------------------------------
__global__ void node_mlp_kernel(const float* __restrict__ x,
                                const float* __restrict__ eps,
                                const float* __restrict__ w1,
                                const float* __restrict__ b1,
                                const float* __restrict__ w2,
                                const float* __restrict__ b2,
                                const float* __restrict__ w3,
                                const float* __restrict__ b3,
                                float* __restrict__ out) {
    __shared__ float sw1[20], sb1[20], sw2[400], sb2[20], sw3[20], sb3;
    int tid = threadIdx.x;
    if (tid < 20) {
        sw1[tid] = w1[tid];
        sb1[tid] = b1[tid];
        sb2[tid] = b2[tid];
        sw3[tid] = w3[tid];
    }
    for (int i = tid; i < 400; i += blockDim.x) sw2[i] = w2[i];
    if (tid == 0) sb3 = b3[0];
    __syncthreads();

    const float e = 1.0f + *eps;

    int i = blockIdx.x * blockDim.x + tid;
    if (i < N_NODES) {
        float s = fmaf(e, x[i], g_agg[i]);   // self-term fused here

        float h1[20];
        #pragma unroll
        for (int j = 0; j < 20; j++)
            h1[j] = fmaxf(fmaf(s, sw1[j], sb1[j]), 0.0f);

        float acc_out = sb3;
        #pragma unroll
        for (int k = 0; k < 20; k++) {
            float a = sb2[k];
            #pragma unroll
            for (int j = 0; j < 20; j++)
                a = fmaf(h1[j], sw2[j * 20 + k], a);
            acc_out = fmaf(fmaxf(a, 0.0f), sw3[k], acc_out);
        }
        out[i] = acc_out;
    }
}

// ---------------------------------------------------------------------------
// Launch. Inputs (metadata order):
//   0: x          [1M]  f32
//   1: edge_index [2, 32M] int32   (src = first 32M, dst = second 32M)
//   2: eps        [1]   f32
//   3: w1 [20]  4: b1 [20]  5: w2 [400]  6: b2 [20]  7: w3 [20]  8: b3 [1]
// Output: [1M] f32
// ---------------------------------------------------------------------------
extern "C" void kernel_launch(void* const* d_in, const int* in_sizes, int n_in,
                              void* d_out, int out_size) {
    const float* x   = (const float*)d_in[0];
    const int*   ei  = (const int*)d_in[1];
    const float* eps = (const float*)d_in[2];
    const float* w1  = (const float*)d_in[3];
    const float* b1  = (const float*)d_in[4];
    const float* w2  = (const float*)d_in[5];
    const float* b2  = (const float*)d_in[6];
    const float* w3  = (const float*)d_in[7];
    const float* b3  = (const float*)d_in[8];
    float* out = (float*)d_out;

    const int4* src4 = (const int4*)ei;                 // first 32M ints
    const int4* dst4 = (const int4*)(ei + N_EDGES);     // second 32M ints

    // 0) zero the aggregation buffer (graph-capturable async memset)
    void* agg_ptr = nullptr;
    cudaGetSymbolAddress(&agg_ptr, g_agg);
    cudaMemsetAsync(agg_ptr, 0, N_NODES * sizeof(float));

    // 1) edge scatter: 8M threads, 4 edges each -> exactly 32M edges
    edge_scatter_kernel<<<N_EDGES / 4 / 256, 256>>>(src4, dst4, x);

    // 2) node MLP (+ fused (1+eps)*x self-term)
    node_mlp_kernel<<<(N_NODES + 255) / 256, 256>>>(x, eps, w1, b1, w2, b2,
                                                    w3, b3, out);
}

// round 6
// speedup vs baseline: 1.1012x; 1.0688x over previous
#include <cuda_runtime.h>
#include <cuda_bf16.h>

#define N_NODES 1000000
#define N_EDGES 32000000
#define BP_MAX  512        // >= max possible kinks (20 + 21*20 = 440)

// Scratch: per-node aggregation buffer + the piecewise-linear MLP table.
__device__ __align__(16) float g_agg[N_NODES];
__device__ float g_bp[BP_MAX];          // sorted kink locations
__device__ float g_segA[BP_MAX + 1];    // per-segment slope
__device__ float g_segC[BP_MAX + 1];    // per-segment intercept
__device__ int   g_nbp;

// ---------------------------------------------------------------------------
// Kernel 1: for each edge (s, d): agg[d] += x[s]
// 4 edges/thread; streaming index loads; RED.E.ADD.F32 (no return trip).
// This kernel is at the per-SM LSU/L1tex wavefront floor (~32 random sectors
// per warp gather + per warp RED) — unchanged from R5.
// ---------------------------------------------------------------------------
__global__ void __launch_bounds__(256)
edge_scatter_kernel(const int4* __restrict__ src4,
                    const int4* __restrict__ dst4,
                    const float* __restrict__ x) {
    int t = blockIdx.x * blockDim.x + threadIdx.x;

    int4 s = __ldcs(src4 + t);
    int4 d = __ldcs(dst4 + t);

    float v0 = __ldg(x + s.x);
    float v1 = __ldg(x + s.y);
    float v2 = __ldg(x + s.z);
    float v3 = __ldg(x + s.w);

    atomicAdd(&g_agg[d.x], v0);
    atomicAdd(&g_agg[d.y], v1);
    atomicAdd(&g_agg[d.z], v2);
    atomicAdd(&g_agg[d.w], v3);
}

// ---------------------------------------------------------------------------
// Kernel 2 (one block, 256 threads): build the exact piecewise-linear form of
//   f(s) = w3^T relu(W2^T relu(s*w1 + b1) + b2) + b3
// Kinks: layer-1 zeros t_j = -b1_j/w1_j, plus layer-2 zeros inside each
// layer-1 interval. Per final segment, (A, C) from active-set linear algebra.
// ---------------------------------------------------------------------------
__global__ void __launch_bounds__(256)
build_pwl_kernel(const float* __restrict__ w1, const float* __restrict__ b1,
                 const float* __restrict__ w2, const float* __restrict__ b2,
                 const float* __restrict__ w3, const float* __restrict__ b3) {
    __shared__ float sw1[20], sb1[20], sw2[400], sb2[20], sw3[20], sb3;
    __shared__ float t1[21];
    __shared__ int   n1, nbp;
    __shared__ float bp[BP_MAX];

    int tid = threadIdx.x;
    if (tid < 20) {
        sw1[tid] = w1[tid]; sb1[tid] = b1[tid];
        sb2[tid] = b2[tid]; sw3[tid] = w3[tid];
    }
    for (int i = tid; i < 400; i += 256) sw2[i] = w2[i];
    if (tid == 0) { sb3 = b3[0]; nbp = 0; }
    __syncthreads();

    // Phase 1+2 (thread 0): layer-1 kinks, sorted (<= 20 elements)
    if (tid == 0) {
        int n = 0;
        for (int j = 0; j < 20; j++)
            if (sw1[j] != 0.0f) t1[n++] = -sb1[j] / sw1[j];
        for (int i = 1; i < n; i++) {              // insertion sort
            float v = t1[i]; int k = i - 1;
            while (k >= 0 && t1[k] > v) { t1[k + 1] = t1[k]; k--; }
            t1[k + 1] = v;
        }
        n1 = n;
        for (int i = 0; i < n; i++) bp[i] = t1[i];
        nbp = n;
    }
    __syncthreads();

    // Phase 3: layer-2 kinks inside each layer-1 interval. (n1+1)*20 tasks.
    int n = n1;
    for (int task = tid; task < (n + 1) * 20; task += 256) {
        int iv = task / 20, k = task % 20;
        float lo = (iv == 0) ? -1e30f : t1[iv - 1];
        float hi = (iv == n) ?  1e30f : t1[iv];
        if (hi <= lo) continue;                    // zero-width interval
        float m;
        if (n == 0)            m = 0.0f;
        else if (iv == 0)      m = hi - 1.0f;
        else if (iv == n)      m = lo + 1.0f;
        else                   m = 0.5f * (lo + hi);

        float alpha = 0.0f, beta = sb2[k];
        for (int j = 0; j < 20; j++) {
            if (fmaf(m, sw1[j], sb1[j]) > 0.0f) {   // h1_j active on interval
                alpha = fmaf(sw1[j], sw2[j * 20 + k], alpha);
                beta  = fmaf(sb1[j], sw2[j * 20 + k], beta);
            }
        }
        if (alpha != 0.0f) {
            float s0 = -beta / alpha;
            if (s0 > lo && s0 < hi) {
                int p = atomicAdd(&nbp, 1);
                if (p < BP_MAX) bp[p] = s0;
            }
        }
    }
    __syncthreads();
    int M = min(nbp, BP_MAX);

    // Phase 4: rank-sort bp -> g_bp (tie-break by original index)
    for (int i = tid; i < M; i += 256) {
        float v = bp[i];
        int r = 0;
        for (int j = 0; j < M; j++) {
            float u = bp[j];
            if (u < v || (u == v && j < i)) r++;
        }
        g_bp[r] = v;
    }
    if (tid == 0) g_nbp = M;
    __syncthreads();

    // Phase 5: per-segment (A, C) by exact active-set propagation at midpoint
    for (int seg = tid; seg <= M; seg += 256) {
        float m;
        if (M == 0)            m = 0.0f;
        else if (seg == 0)     m = g_bp[0] - 1.0f;
        else if (seg == M)     m = g_bp[M - 1] + 1.0f;
        else                   m = 0.5f * (g_bp[seg - 1] + g_bp[seg]);

        float A = 0.0f, C = sb3;
        for (int k = 0; k < 20; k++) {
            float alpha = 0.0f, beta = sb2[k];
            for (int j = 0; j < 20; j++) {
                if (fmaf(m, sw1[j], sb1[j]) > 0.0f) {
                    alpha = fmaf(sw1[j], sw2[j * 20 + k], alpha);
                    beta  = fmaf(sb1[j], sw2[j * 20 + k], beta);
                }
            }
            if (fmaf(m, alpha, beta) > 0.0f) {      // h2_k active
                A = fmaf(alpha, sw3[k], A);
                C = fmaf(beta,  sw3[k], C);
            }
        }
        g_segA[seg] = A;
        g_segC[seg] = C;
    }
}

// ---------------------------------------------------------------------------
// Kernel 3: out[i] = PWL((1+eps)*x[i] + agg[i])
// 4 nodes/thread (float4), smem binary search + 1 FMA per node. Streaming.
// ---------------------------------------------------------------------------
__device__ __forceinline__ float pwl_eval(float s, const float* __restrict__ sbp,
                                          const float* __restrict__ sA,
                                          const float* __restrict__ sC, int M) {
    int lo = 0, hi = M;
    while (lo < hi) {
        int mid = (lo + hi) >> 1;
        if (s >= sbp[mid]) lo = mid + 1; else hi = mid;
    }
    return fmaf(sA[lo], s, sC[lo]);
}

__global__ void __launch_bounds__(256)
node_pwl_kernel(const float* __restrict__ x,
                const float* __restrict__ eps,
                float* __restrict__ out) {
    __shared__ float sbp[BP_MAX], sA[BP_MAX + 1], sC[BP_MAX + 1];
    __shared__ int sM;
    int tid = threadIdx.x;
    if (tid == 0) sM = g_nbp;
    __syncthreads();
    int M = sM;
    for (int i = tid; i < M; i += 256) sbp[i] = g_bp[i];
    for (int i = tid; i <= M; i += 256) { sA[i] = g_segA[i]; sC[i] = g_segC[i]; }
    __syncthreads();

    const float e = 1.0f + *eps;
    int idx = (blockIdx.x * blockDim.x + tid) * 4;
    if (idx < N_NODES) {                 // N_NODES % 4 == 0 -> float4 in-bounds
        float4 xv = *reinterpret_cast<const float4*>(x + idx);
        float4 av = *reinterpret_cast<const float4*>(g_agg + idx);
        float4 r;
        r.x = pwl_eval(fmaf(e, xv.x, av.x), sbp, sA, sC, M);
        r.y = pwl_eval(fmaf(e, xv.y, av.y), sbp, sA, sC, M);
        r.z = pwl_eval(fmaf(e, xv.z, av.z), sbp, sA, sC, M);
        r.w = pwl_eval(fmaf(e, xv.w, av.w), sbp, sA, sC, M);
        *reinterpret_cast<float4*>(out + idx) = r;
    }
}

// ---------------------------------------------------------------------------
// Launch. Inputs (metadata order):
//   0: x [1M] f32   1: edge_index [2,32M] int32   2: eps [1] f32
//   3: w1 [20] 4: b1 [20] 5: w2 [400] 6: b2 [20] 7: w3 [20] 8: b3 [1]
// Output: [1M] f32
// ---------------------------------------------------------------------------
extern "C" void kernel_launch(void* const* d_in, const int* in_sizes, int n_in,
                              void* d_out, int out_size) {
    const float* x   = (const float*)d_in[0];
    const int*   ei  = (const int*)d_in[1];
    const float* eps = (const float*)d_in[2];
    const float* w1  = (const float*)d_in[3];
    const float* b1  = (const float*)d_in[4];
    const float* w2  = (const float*)d_in[5];
    const float* b2  = (const float*)d_in[6];
    const float* w3  = (const float*)d_in[7];
    const float* b3  = (const float*)d_in[8];
    float* out = (float*)d_out;

    const int4* src4 = (const int4*)ei;              // first 32M ints
    const int4* dst4 = (const int4*)(ei + N_EDGES);  // second 32M ints

    // 0) zero the aggregation buffer (graph-capturable async memset)
    void* agg_ptr = nullptr;
    cudaGetSymbolAddress(&agg_ptr, g_agg);
    cudaMemsetAsync(agg_ptr, 0, N_NODES * sizeof(float));

    // 1) build the piecewise-linear MLP table (one block, ~3us)
    build_pwl_kernel<<<1, 256>>>(w1, b1, w2, b2, w3, b3);

    // 2) edge scatter: 8M threads, 4 edges each -> exactly 32M edges
    edge_scatter_kernel<<<N_EDGES / 4 / 256, 256>>>(src4, dst4, x);

    // 3) node pass: PWL eval, 4 nodes/thread, pure streaming
    node_pwl_kernel<<<(N_NODES / 4 + 255) / 256, 256>>>(x, eps, out);
}

// round 9
// speedup vs baseline: 1.1550x; 1.0489x over previous
#include <cuda_runtime.h>
#include <cuda_bf16.h>

#define N_NODES 1000000
#define N_EDGES 32000000
#define BP_MAX  512        // >= max possible kinks (20 + 21*20 = 440)

// Scratch: per-node aggregation buffer + the piecewise-linear MLP table.
__device__ __align__(16) float g_agg[N_NODES];
__device__ float g_bp[BP_MAX];          // sorted kink locations
__device__ float g_segA[BP_MAX + 1];    // per-segment slope
__device__ float g_segC[BP_MAX + 1];    // per-segment intercept
__device__ int   g_nbp;

// ---------------------------------------------------------------------------
// PWL builder (runs in ONE block): exact piecewise-linear form of
//   f(s) = w3^T relu(W2^T relu(s*w1 + b1) + b2) + b3
// Kinks: layer-1 zeros t_j = -b1_j/w1_j, plus layer-2 zeros inside each
// layer-1 interval. Per final segment, (A, C) from active-set linear algebra.
// ---------------------------------------------------------------------------
__device__ void build_pwl_block(const float* __restrict__ w1,
                                const float* __restrict__ b1,
                                const float* __restrict__ w2,
                                const float* __restrict__ b2,
                                const float* __restrict__ w3,
                                const float* __restrict__ b3) {
    __shared__ float sw1[20], sb1[20], sw2[400], sb2[20], sw3[20], sb3;
    __shared__ float t1[21];
    __shared__ int   n1, nbp;
    __shared__ float bp[BP_MAX];

    int tid = threadIdx.x;
    if (tid < 20) {
        sw1[tid] = w1[tid]; sb1[tid] = b1[tid];
        sb2[tid] = b2[tid]; sw3[tid] = w3[tid];
    }
    for (int i = tid; i < 400; i += 256) sw2[i] = w2[i];
    if (tid == 0) { sb3 = b3[0]; nbp = 0; }
    __syncthreads();

    // Phase 1+2 (thread 0): layer-1 kinks, sorted (<= 20 elements)
    if (tid == 0) {
        int n = 0;
        for (int j = 0; j < 20; j++)
            if (sw1[j] != 0.0f) t1[n++] = -sb1[j] / sw1[j];
        for (int i = 1; i < n; i++) {              // insertion sort
            float v = t1[i]; int k = i - 1;
            while (k >= 0 && t1[k] > v) { t1[k + 1] = t1[k]; k--; }
            t1[k + 1] = v;
        }
        n1 = n;
        for (int i = 0; i < n; i++) bp[i] = t1[i];
        nbp = n;
    }
    __syncthreads();

    // Phase 3: layer-2 kinks inside each layer-1 interval. (n1+1)*20 tasks.
    int n = n1;
    for (int task = tid; task < (n + 1) * 20; task += 256) {
        int iv = task / 20, k = task % 20;
        float lo = (iv == 0) ? -1e30f : t1[iv - 1];
        float hi = (iv == n) ?  1e30f : t1[iv];
        if (hi <= lo) continue;                    // zero-width interval
        float m;
        if (n == 0)            m = 0.0f;
        else if (iv == 0)      m = hi - 1.0f;
        else if (iv == n)      m = lo + 1.0f;
        else                   m = 0.5f * (lo + hi);

        float alpha = 0.0f, beta = sb2[k];
        for (int j = 0; j < 20; j++) {
            if (fmaf(m, sw1[j], sb1[j]) > 0.0f) {   // h1_j active on interval
                alpha = fmaf(sw1[j], sw2[j * 20 + k], alpha);
                beta  = fmaf(sb1[j], sw2[j * 20 + k], beta);
            }
        }
        if (alpha != 0.0f) {
            float s0 = -beta / alpha;
            if (s0 > lo && s0 < hi) {
                int p = atomicAdd(&nbp, 1);
                if (p < BP_MAX) bp[p] = s0;
            }
        }
    }
    __syncthreads();
    int M = min(nbp, BP_MAX);

    // Phase 4: rank-sort bp -> g_bp (tie-break by original index)
    for (int i = tid; i < M; i += 256) {
        float v = bp[i];
        int r = 0;
        for (int j = 0; j < M; j++) {
            float u = bp[j];
            if (u < v || (u == v && j < i)) r++;
        }
        g_bp[r] = v;
    }
    if (tid == 0) g_nbp = M;
    __syncthreads();

    // Phase 5: per-segment (A, C) by exact active-set propagation at midpoint
    for (int seg = tid; seg <= M; seg += 256) {
        float m;
        if (M == 0)            m = 0.0f;
        else if (seg == 0)     m = g_bp[0] - 1.0f;
        else if (seg == M)     m = g_bp[M - 1] + 1.0f;
        else                   m = 0.5f * (g_bp[seg - 1] + g_bp[seg]);

        float A = 0.0f, C = sb3;
        for (int k = 0; k < 20; k++) {
            float alpha = 0.0f, beta = sb2[k];
            for (int j = 0; j < 20; j++) {
                if (fmaf(m, sw1[j], sb1[j]) > 0.0f) {
                    alpha = fmaf(sw1[j], sw2[j * 20 + k], alpha);
                    beta  = fmaf(sb1[j], sw2[j * 20 + k], beta);
                }
            }
            if (fmaf(m, alpha, beta) > 0.0f) {      // h2_k active
                A = fmaf(alpha, sw3[k], A);
                C = fmaf(beta,  sw3[k], C);
            }
        }
        g_segA[seg] = A;
        g_segC[seg] = C;
    }
}

// ---------------------------------------------------------------------------
// Fused kernel: block 0 builds the PWL table (~17us, hidden under the
// ~240us scatter); blocks 1..N scatter 4 edges/thread.
// Streaming index loads; RED.E.ADD.F32 (no return trip). The scatter is at
// the LTS 32B-sector floor (~2GB of gather+atomic sector traffic).
// __launch_bounds__(256, 4) caps regs at 64 so the build path's register
// appetite doesn't cut edge-block occupancy.
// ---------------------------------------------------------------------------
__global__ void __launch_bounds__(256, 4)
edge_scatter_build_kernel(const int4* __restrict__ src4,
                          const int4* __restrict__ dst4,
                          const float* __restrict__ x,
                          const float* __restrict__ w1,
                          const float* __restrict__ b1,
                          const float* __restrict__ w2,
                          const float* __restrict__ b2,
                          const float* __restrict__ w3,
                          const float* __restrict__ b3) {
    if (blockIdx.x == 0) {
        build_pwl_block(w1, b1, w2, b2, w3, b3);
        return;
    }

    int t = (blockIdx.x - 1) * blockDim.x + threadIdx.x;

    int4 s = __ldcs(src4 + t);
    int4 d = __ldcs(dst4 + t);

    float v0 = __ldg(x + s.x);
    float v1 = __ldg(x + s.y);
    float v2 = __ldg(x + s.z);
    float v3 = __ldg(x + s.w);

    atomicAdd(&g_agg[d.x], v0);
    atomicAdd(&g_agg[d.y], v1);
    atomicAdd(&g_agg[d.z], v2);
    atomicAdd(&g_agg[d.w], v3);
}

// ---------------------------------------------------------------------------
// Node pass: out[i] = PWL((1+eps)*x[i] + agg[i])
// 4 nodes/thread (float4), smem binary search + 1 FMA per node. Streaming.
// ---------------------------------------------------------------------------
__device__ __forceinline__ float pwl_eval(float s, const float* __restrict__ sbp,
                                          const float* __restrict__ sA,
                                          const float* __restrict__ sC, int M) {
    int lo = 0, hi = M;
    while (lo < hi) {
        int mid = (lo + hi) >> 1;
        if (s >= sbp[mid]) lo = mid + 1; else hi = mid;
    }
    return fmaf(sA[lo], s, sC[lo]);
}

__global__ void __launch_bounds__(256)
node_pwl_kernel(const float* __restrict__ x,
                const float* __restrict__ eps,
                float* __restrict__ out) {
    __shared__ float sbp[BP_MAX], sA[BP_MAX + 1], sC[BP_MAX + 1];
    __shared__ int sM;
    int tid = threadIdx.x;
    if (tid == 0) sM = g_nbp;
    __syncthreads();
    int M = sM;
    for (int i = tid; i < M; i += 256) sbp[i] = g_bp[i];
    for (int i = tid; i <= M; i += 256) { sA[i] = g_segA[i]; sC[i] = g_segC[i]; }
    __syncthreads();

    const float e = 1.0f + *eps;
    int idx = (blockIdx.x * blockDim.x + tid) * 4;
    if (idx < N_NODES) {                 // N_NODES % 4 == 0 -> float4 in-bounds
        float4 xv = *reinterpret_cast<const float4*>(x + idx);
        float4 av = *reinterpret_cast<const float4*>(g_agg + idx);
        float4 r;
        r.x = pwl_eval(fmaf(e, xv.x, av.x), sbp, sA, sC, M);
        r.y = pwl_eval(fmaf(e, xv.y, av.y), sbp, sA, sC, M);
        r.z = pwl_eval(fmaf(e, xv.z, av.z), sbp, sA, sC, M);
        r.w = pwl_eval(fmaf(e, xv.w, av.w), sbp, sA, sC, M);
        *reinterpret_cast<float4*>(out + idx) = r;
    }
}

// ---------------------------------------------------------------------------
// Launch. Inputs (metadata order):
//   0: x [1M] f32   1: edge_index [2,32M] int32   2: eps [1] f32
//   3: w1 [20] 4: b1 [20] 5: w2 [400] 6: b2 [20] 7: w3 [20] 8: b3 [1]
// Output: [1M] f32
// ---------------------------------------------------------------------------
extern "C" void kernel_launch(void* const* d_in, const int* in_sizes, int n_in,
                              void* d_out, int out_size) {
    const float* x   = (const float*)d_in[0];
    const int*   ei  = (const int*)d_in[1];
    const float* eps = (const float*)d_in[2];
    const float* w1  = (const float*)d_in[3];
    const float* b1  = (const float*)d_in[4];
    const float* w2  = (const float*)d_in[5];
    const float* b2  = (const float*)d_in[6];
    const float* w3  = (const float*)d_in[7];
    const float* b3  = (const float*)d_in[8];
    float* out = (float*)d_out;

    const int4* src4 = (const int4*)ei;              // first 32M ints
    const int4* dst4 = (const int4*)(ei + N_EDGES);  // second 32M ints

    // 0) zero the aggregation buffer (graph-capturable async memset)
    void* agg_ptr = nullptr;
    cudaGetSymbolAddress(&agg_ptr, g_agg);
    cudaMemsetAsync(agg_ptr, 0, N_NODES * sizeof(float));

    // 1) fused: block 0 builds PWL table (hidden), blocks 1..31250 scatter
    edge_scatter_build_kernel<<<N_EDGES / 4 / 256 + 1, 256>>>(
        src4, dst4, x, w1, b1, w2, b2, w3, b3);

    // 2) node pass: PWL eval, 4 nodes/thread, pure streaming
    node_pwl_kernel<<<(N_NODES / 4 + 255) / 256, 256>>>(x, eps, out);
}